// round 9
// baseline (speedup 1.0000x reference)
#include <cuda_runtime.h>

#define C_N 5000
#define NT  40                      // ceil(5000/128) col tiles

typedef unsigned long long ull;

__device__ __forceinline__ ull dup2(float x) {
    ull r; asm("mov.b64 %0,{%1,%1};" : "=l"(r) : "r"(__float_as_uint(x)));
    return r;
}
__device__ __forceinline__ ull fma2(ull a, ull b, ull c) {
    ull d; asm("fma.rn.f32x2 %0,%1,%2,%3;" : "=l"(d) : "l"(a), "l"(b), "l"(c));
    return d;
}
__device__ __forceinline__ void unpack2(ull v, float& x, float& y) {
    unsigned lo, hi;
    asm("mov.b64 {%0,%1},%2;" : "=r"(lo), "=r"(hi) : "l"(v));
    x = __uint_as_float(lo); y = __uint_as_float(hi);
}

// ---------------------------------------------------------------------------
// K1: xcT[kout][class] = (c_feat @ (W2+W3) + b2+b3)^T  into input-buffer
// scratch. 313 blocks x 128 threads (thread = kout), 16 classes per block.
// ---------------------------------------------------------------------------
__global__ void __launch_bounds__(128, 1) k1_kernel(
    const float* __restrict__ X,  const float* __restrict__ Wa,
    const float* __restrict__ Wb, const float* __restrict__ ba,
    const float* __restrict__ bb, float* __restrict__ outT)
{
    __shared__ float Ws[64 * 128];
    __shared__ float Xs[16 * 64];
    const int tid = threadIdx.x, c = tid, r0 = blockIdx.x * 16;
    const float bias = ba[c] + bb[c];
    float acc[16];
#pragma unroll
    for (int r = 0; r < 16; r++) acc[r] = bias;

    for (int kc = 0; kc < 2; kc++) {
        for (int i = tid; i < 64 * 128; i += 128) {
            int kl = i >> 7, cc = i & 127;
            Ws[i] = Wa[(kc * 64 + kl) * 128 + cc] + Wb[(kc * 64 + kl) * 128 + cc];
        }
        for (int i = tid; i < 16 * 64; i += 128) {
            int r = i >> 6, kl = i & 63, gr = r0 + r;
            Xs[i] = (gr < C_N) ? X[(size_t)gr * 128 + kc * 64 + kl] : 0.f;
        }
        __syncthreads();
#pragma unroll 8
        for (int kl = 0; kl < 64; kl++) {
            float w = Ws[kl * 128 + c];
#pragma unroll
            for (int r = 0; r < 16; r++)
                acc[r] = fmaf(Xs[r * 64 + kl], w, acc[r]);
        }
        __syncthreads();
    }
#pragma unroll
    for (int r = 0; r < 16; r++) {
        int gr = r0 + r;
        if (gr < C_N) outT[(size_t)c * C_N + gr] = acc[r];
    }
}

// ---------------------------------------------------------------------------
// K2 (fused): each block owns 32 method rows. Phase 1: x_m tile in smem
// (proj + own-edge scatter + transpose). Phase 2: GEMM vs xcT over 40 col
// tiles with online per-row (max, sumexp). Phase 3: normalize own rows.
// 48 KB static smem, 256 threads, 625 blocks (625*32 == 20000).
// ---------------------------------------------------------------------------
__global__ void __launch_bounds__(256, 1) k2_kernel(
    const float* __restrict__ m_feat,  const float* __restrict__ W1,
    const float* __restrict__ b1,      const float* __restrict__ own_val,
    const int*   __restrict__ own_row, const int* __restrict__ own_col,
    const float* __restrict__ c_feat,  const float* __restrict__ xcT,
    float* __restrict__ outp)
{
    __shared__ float sm[12288];          // 48 KB, regions aliased by phase
    float*  xm   = sm;                   // [32 rows][128 k]  (phase 1)
    float*  xmT  = sm + 4096;            // [128 k][32 rows]  (phase 2)
    float*  Bs   = sm + 8192;            // [32 k][128 cols]  (phase 2)
    float*  Ws   = sm + 4096;            // [32 k][128 kout]  (phase 1, = xmT)
    float*  Xs   = sm + 8192;            // [32 rows][32 k]   (phase 1, = Bs)
    float2* rms  = (float2*)sm;          // [32] row stats    (overlays dead xm)

    const int tid = threadIdx.x;
    const int r0  = blockIdx.x * 32;

    // ---- Phase 1a: projection  xm[r][c] = m_feat[r0+r] @ W1 + b1 ----
    {
        const int c = tid & 127, h = tid >> 7;    // h: rows h*16..h*16+15
        const float bias = b1[c];
        float acc[16];
#pragma unroll
        for (int r = 0; r < 16; r++) acc[r] = 0.f;
        for (int kc = 0; kc < 4; kc++) {
            for (int t = 0; t < 16; t++) {
                int i = tid + t * 256;            // 4096 W floats
                int kl = i >> 7, cc = i & 127;
                Ws[i] = W1[(kc * 32 + kl) * 128 + cc];
            }
            for (int t = 0; t < 4; t++) {
                int i = tid + t * 256;            // 1024 X floats
                int r = i >> 5, kl = i & 31;
                Xs[i] = m_feat[(size_t)(r0 + r) * 128 + kc * 32 + kl];
            }
            __syncthreads();
#pragma unroll 8
            for (int kl = 0; kl < 32; kl++) {
                float w = Ws[kl * 128 + c];
#pragma unroll
                for (int r = 0; r < 16; r++)
                    acc[r] = fmaf(Xs[(h * 16 + r) * 32 + kl], w, acc[r]);
            }
            __syncthreads();
        }
#pragma unroll
        for (int r = 0; r < 16; r++)
            xm[(h * 16 + r) * 128 + c] = acc[r] + bias;
    }
    __syncthreads();

    // ---- Phase 1b: own-edge scatter into xm (rows are block-exclusive) ----
    for (int e = tid; e < 20000; e += 256) {
        int r = own_row[e] - r0;
        if ((unsigned)r < 32u) {
            float v = own_val[e];
            const float4* cp = (const float4*)(c_feat + (size_t)own_col[e] * 128);
#pragma unroll 4
            for (int j = 0; j < 32; j++) {
                float4 f = cp[j];
                atomicAdd(&xm[r * 128 + j * 4 + 0], v * f.x);
                atomicAdd(&xm[r * 128 + j * 4 + 1], v * f.y);
                atomicAdd(&xm[r * 128 + j * 4 + 2], v * f.z);
                atomicAdd(&xm[r * 128 + j * 4 + 3], v * f.w);
            }
        }
    }
    __syncthreads();

    // ---- Phase 1c: transpose xm -> xmT, then init row stats ----
    for (int t = 0; t < 16; t++) {
        int i = tid + t * 256;                    // 4096 elements
        int k = i >> 5, r = i & 31;
        xmT[k * 32 + r] = xm[r * 128 + k];
    }
    __syncthreads();                              // xm now dead
    if (tid < 32) rms[tid] = make_float2(__int_as_float(0xff800000), 0.f);
    __syncthreads();

    // ---- Phase 2: GEMM over 40 col tiles, online softmax stats ----
    const int tx = tid & 15;                      // cols tx*8 .. tx*8+7
    const int ty = tid >> 4;                      // rows 2ty, 2ty+1
    for (int ct = 0; ct < NT; ct++) {
        const int c0 = ct * 128;
        ull a00, a01, a02, a03, a10, a11, a12, a13;
        a00 = a01 = a02 = a03 = a10 = a11 = a12 = a13 = 0ull;

        for (int kc = 0; kc < 4; kc++) {
            __syncthreads();                      // Bs free of prior readers
            for (int t = 0; t < 4; t++) {
                int f = tid + t * 256;            // 1024 float4 slots
                int kl = f >> 5, c4 = f & 31;
                int col = c0 + c4 * 4;
                float4 v = make_float4(0.f, 0.f, 0.f, 0.f);
                if (col < C_N)
                    v = *(const float4*)&xcT[(size_t)(kc * 32 + kl) * C_N + col];
                *(float4*)&Bs[kl * 128 + c4 * 4] = v;
            }
            __syncthreads();
#pragma unroll 4
            for (int kl = 0; kl < 32; kl++) {
                float2 ap = *(const float2*)&xmT[(kc * 32 + kl) * 32 + 2 * ty];
                ull d0 = dup2(ap.x), d1 = dup2(ap.y);
                ulonglong2 q0 = *(const ulonglong2*)&Bs[kl * 128 + tx * 8];
                ulonglong2 q1 = *(const ulonglong2*)&Bs[kl * 128 + tx * 8 + 4];
                a00 = fma2(d0, q0.x, a00); a01 = fma2(d0, q0.y, a01);
                a02 = fma2(d0, q1.x, a02); a03 = fma2(d0, q1.y, a03);
                a10 = fma2(d1, q0.x, a10); a11 = fma2(d1, q0.y, a11);
                a12 = fma2(d1, q1.x, a12); a13 = fma2(d1, q1.y, a13);
            }
        }

        // epilogue: store raw scores + merge per-row (max, sumexp)
        const int cb = c0 + tx * 8;               // 8-col group; 5000%8==0 ->
        const bool ok = (cb < C_N);               // group fully valid or not
#pragma unroll
        for (int p = 0; p < 2; p++) {
            int row = 2 * ty + p;
            float s0, s1, s2, s3, s4, s5, s6, s7;
            if (p == 0) {
                unpack2(a00, s0, s1); unpack2(a01, s2, s3);
                unpack2(a02, s4, s5); unpack2(a03, s6, s7);
            } else {
                unpack2(a10, s0, s1); unpack2(a11, s2, s3);
                unpack2(a12, s4, s5); unpack2(a13, s6, s7);
            }
            if (ok) {
                size_t ob = (size_t)(r0 + row) * C_N + cb;
                *(float4*)&outp[ob]     = make_float4(s0, s1, s2, s3);
                *(float4*)&outp[ob + 4] = make_float4(s4, s5, s6, s7);
            }
            float m = __int_as_float(0xff800000);
            if (ok) {
                m = fmaxf(fmaxf(fmaxf(s0, s1), fmaxf(s2, s3)),
                          fmaxf(fmaxf(s4, s5), fmaxf(s6, s7)));
            }
#pragma unroll
            for (int d = 1; d < 16; d <<= 1)
                m = fmaxf(m, __shfl_xor_sync(0xffffffffu, m, d));
            float pp = 0.f;
            if (ok) {
                pp = __expf(s0 - m) + __expf(s1 - m) + __expf(s2 - m) +
                     __expf(s3 - m) + __expf(s4 - m) + __expf(s5 - m) +
                     __expf(s6 - m) + __expf(s7 - m);
            }
#pragma unroll
            for (int d = 1; d < 16; d <<= 1)
                pp += __shfl_xor_sync(0xffffffffu, pp, d);
            if (tx == 0) {                        // unique owner lane per row
                float2 o = rms[row];
                float mn = fmaxf(o.x, m);
                o.y = o.y * __expf(o.x - mn) + pp * __expf(m - mn);
                o.x = mn;
                rms[row] = o;
            }
        }
    }
    __syncthreads();                              // rms final & visible

    // ---- Phase 3: normalize own 32x5000 slice in place ----
    for (int i = tid; i < 40000; i += 256) {      // 40000 float4 = 32*1250
        int row = i / 1250;
        float2 ms = rms[row];
        float inv = 1.f / ms.y;
        float4* p4 = (float4*)outp + (size_t)(r0 + row) * 1250 + (i - row * 1250);
        float4 v = *p4;
        v.x = __expf(v.x - ms.x) * inv;
        v.y = __expf(v.y - ms.x) * inv;
        v.z = __expf(v.z - ms.x) * inv;
        v.w = __expf(v.w - ms.x) * inv;
        *p4 = v;
    }
}

// ---------------------------------------------------------------------------
// Launch. Scratch for x_c^T lives in the UNUSED mc_call_row input buffer
// (call edges are dead in the collapsed math; 640000 int32 == 128*5000
// floats exactly). Rewritten fully every call -> deterministic.
// ---------------------------------------------------------------------------
extern "C" void kernel_launch(void* const* d_in, const int* in_sizes, int n_in,
                              void* d_out, int out_size)
{
    const float* m_feat  = (const float*)d_in[0];
    const float* c_feat  = (const float*)d_in[1];
    const float* own_val = (const float*)d_in[2];
    const float* W1 = (const float*)d_in[3];
    const float* b1 = (const float*)d_in[6];
    const float* W2 = (const float*)d_in[7];
    const float* b2 = (const float*)d_in[10];
    const float* W3 = (const float*)d_in[11];
    const float* b3 = (const float*)d_in[14];
    const int* own_row = (const int*)d_in[15];
    const int* own_col = (const int*)d_in[16];
    float* xcT = (float*)d_in[17];       // dead input -> x_c^T scratch
    float* outp = (float*)d_out;

    k1_kernel<<<313, 128>>>(c_feat, W2, W3, b2, b3, xcT);
    k2_kernel<<<625, 256>>>(m_feat, W1, b1, own_val, own_row, own_col,
                            c_feat, xcT, outp);
}

// round 11
// speedup vs baseline: 2.4656x; 2.4656x over previous
#include <cuda_runtime.h>
#include <cstdint>

#define C_N   5000
#define E_OWN 20000

typedef unsigned long long ull;

__device__ __forceinline__ ull dup2(float x) {
    ull r; asm("mov.b64 %0,{%1,%1};" : "=l"(r) : "r"(__float_as_uint(x)));
    return r;
}
__device__ __forceinline__ ull fma2(ull a, ull b, ull c) {
    ull d; asm("fma.rn.f32x2 %0,%1,%2,%3;" : "=l"(d) : "l"(a), "l"(b), "l"(c));
    return d;
}
__device__ __forceinline__ void unpack2(ull v, float& x, float& y) {
    unsigned lo, hi;
    asm("mov.b64 {%0,%1},%2;" : "=r"(lo), "=r"(hi) : "l"(v));
    x = __uint_as_float(lo); y = __uint_as_float(hi);
}
__device__ __forceinline__ uint32_t su32(const void* p) {
    uint32_t a;
    asm("{.reg .u64 t; cvta.to.shared.u64 t,%1; cvt.u32.u64 %0,t;}"
        : "=r"(a) : "l"(p));
    return a;
}

// ---------------------------------------------------------------------------
// K1: xcT[kout][class] = (c_feat @ (W2+W3) + b2+b3)^T into input-buffer
// scratch (dead mc_call_row). 313 blocks x 128 threads. (verified in R9)
// ---------------------------------------------------------------------------
__global__ void __launch_bounds__(128, 1) k1_kernel(
    const float* __restrict__ X,  const float* __restrict__ Wa,
    const float* __restrict__ Wb, const float* __restrict__ ba,
    const float* __restrict__ bb, float* __restrict__ outT)
{
    __shared__ float Ws[64 * 128];
    __shared__ float Xs[16 * 64];
    const int tid = threadIdx.x, c = tid, r0 = blockIdx.x * 16;
    const float bias = ba[c] + bb[c];
    float acc[16];
#pragma unroll
    for (int r = 0; r < 16; r++) acc[r] = bias;

    for (int kc = 0; kc < 2; kc++) {
        for (int i = tid; i < 64 * 128; i += 128) {
            int kl = i >> 7, cc = i & 127;
            Ws[i] = Wa[(kc * 64 + kl) * 128 + cc] + Wb[(kc * 64 + kl) * 128 + cc];
        }
        for (int i = tid; i < 16 * 64; i += 128) {
            int r = i >> 6, kl = i & 63, gr = r0 + r;
            Xs[i] = (gr < C_N) ? X[(size_t)gr * 128 + kc * 64 + kl] : 0.f;
        }
        __syncthreads();
#pragma unroll 8
        for (int kl = 0; kl < 64; kl++) {
            float w = Ws[kl * 128 + c];
#pragma unroll
            for (int r = 0; r < 16; r++)
                acc[r] = fmaf(Xs[r * 64 + kl], w, acc[r]);
        }
        __syncthreads();
    }
#pragma unroll
    for (int r = 0; r < 16; r++) {
        int gr = r0 + r;
        if (gr < C_N) outT[(size_t)c * C_N + gr] = acc[r];
    }
}

// ---------------------------------------------------------------------------
// K2 (fused): block owns 32 method rows (625 blocks, 625*32 == 20000).
//  Phase 1: x_m^T panel [128k][32r] in smem (proj + own-edge scatter).
//  Phase 2: S-tile GEMM over 40 col tiles of 128, cp.async double-buffered
//           B chunks [32k][128c]; per-thread 8 rows x 2 cols (8 FFMA2/k);
//           per-warp register-resident online (rowmax, rowsumexp).
//  Phase 3: merge stats, normalize own 32x5000 slice in place.
// smem: xmT 16KB + Bs 2x16KB = 48KB exactly. 3 blocks/SM target.
// ---------------------------------------------------------------------------
__global__ void __launch_bounds__(256, 3) k2_kernel(
    const float* __restrict__ m_feat,  const float* __restrict__ W1,
    const float* __restrict__ b1,      const float* __restrict__ own_val,
    const int*   __restrict__ own_row, const int* __restrict__ own_col,
    const float* __restrict__ c_feat,  const float* __restrict__ xcT,
    float* __restrict__ outp)
{
    __shared__ __align__(16) float sm[12288];     // 48 KB
    float* xmT = sm;                              // [128k][32r]   4096 f
    float* Bs  = sm + 4096;                       // 2 x [32k][128c] 8192 f
    float* Wsp = sm + 4096;                       // phase1 alias: W chunk
    float* Xsp = sm + 8192;                       // phase1 alias: X chunk

    const int tid = threadIdx.x;
    const int r0  = blockIdx.x * 32;

    // ---- Phase 1a: projection, written transposed into xmT ----
    {
        const int c = tid & 127, h = tid >> 7;    // h: rows h*16..h*16+15
        float acc[16];
#pragma unroll
        for (int r = 0; r < 16; r++) acc[r] = 0.f;
        for (int kc = 0; kc < 4; kc++) {
#pragma unroll
            for (int t = 0; t < 16; t++) {
                int i = tid + t * 256;            // 4096 W floats
                int kl = i >> 7, cc = i & 127;
                Wsp[i] = W1[(kc * 32 + kl) * 128 + cc];
            }
#pragma unroll
            for (int t = 0; t < 4; t++) {
                int i = tid + t * 256;            // 1024 X floats
                int r = i >> 5, kl = i & 31;
                Xsp[i] = m_feat[(size_t)(r0 + r) * 128 + kc * 32 + kl];
            }
            __syncthreads();
#pragma unroll 8
            for (int kl = 0; kl < 32; kl++) {
                float w = Wsp[kl * 128 + c];
#pragma unroll
                for (int r = 0; r < 16; r++)
                    acc[r] = fmaf(Xsp[(h * 16 + r) * 32 + kl], w, acc[r]);
            }
            __syncthreads();
        }
        const float bias = b1[c];
#pragma unroll
        for (int r = 0; r < 16; r++)
            xmT[c * 32 + h * 16 + r] = acc[r] + bias;
    }
    __syncthreads();

    // ---- Phase 1b: own-edge scatter into xmT (rows block-exclusive) ----
    for (int e = tid; e < E_OWN; e += 256) {
        int r = own_row[e] - r0;
        if ((unsigned)r < 32u) {
            float v = own_val[e];
            const float4* cp = (const float4*)(c_feat + (size_t)own_col[e] * 128);
#pragma unroll 4
            for (int j = 0; j < 32; j++) {
                float4 f = cp[j];
                atomicAdd(&xmT[(j * 4 + 0) * 32 + r], v * f.x);
                atomicAdd(&xmT[(j * 4 + 1) * 32 + r], v * f.y);
                atomicAdd(&xmT[(j * 4 + 2) * 32 + r], v * f.z);
                atomicAdd(&xmT[(j * 4 + 3) * 32 + r], v * f.w);
            }
        }
    }

    // ---- Phase 2: pipelined GEMM + online softmax ----
    const int tx = tid & 63;          // col pair: cols {2tx, 2tx+1} in tile
    const int ty = tid >> 6;          // rows ty*8 .. ty*8+7 (const per warp)
    const float NEG = __int_as_float(0xff800000);

    float ms[8], ps[8];               // per-row (max, sumexp), warp-owned
#pragma unroll
    for (int r = 0; r < 8; r++) { ms[r] = NEG; ps[r] = 0.f; }

    ull u00 = 0, u01 = 0, u10 = 0, u11 = 0, u20 = 0, u21 = 0, u30 = 0, u31 = 0;

    // stage chunk h (h = ct*4+kc) into Bs[(h&1)]
#define STAGE(H) do {                                                        \
    int _h = (H);                                                            \
    float* _dst = Bs + ((_h & 1) << 12);                                     \
    int _kb = (_h & 3) * 32, _c0 = (_h >> 2) * 128;                          \
    _Pragma("unroll")                                                        \
    for (int _t = 0; _t < 4; _t++) {                                         \
        int _f = tid + _t * 256;                                             \
        int _kl = _f >> 5, _c4 = _f & 31;                                    \
        int _col = _c0 + _c4 * 4;                                            \
        int _sz = (_col < C_N) ? 16 : 0;                                     \
        const float* _src = xcT + (size_t)(_kb + _kl) * C_N                  \
                            + (_col < C_N ? _col : 0);                       \
        uint32_t _sa = su32(_dst + _kl * 128 + _c4 * 4);                     \
        asm volatile("cp.async.cg.shared.global [%0], [%1], 16, %2;"         \
                     :: "r"(_sa), "l"(_src), "r"(_sz));                      \
    }                                                                        \
} while (0)

    STAGE(0);
    asm volatile("cp.async.commit_group;");

    for (int g = 0; g < 160; g++) {
        if (g < 159) {
            STAGE(g + 1);
            asm volatile("cp.async.commit_group;");
            asm volatile("cp.async.wait_group 1;");
        } else {
            asm volatile("cp.async.wait_group 0;");
        }
        __syncthreads();

        const float* bs = Bs + ((g & 1) << 12);
        const int kc = g & 3;
#pragma unroll 8
        for (int kl = 0; kl < 32; kl++) {
            const float* ab = &xmT[(kc * 32 + kl) * 32 + ty * 8];
            ulonglong2 A0 = *(const ulonglong2*)ab;         // row pairs 0,1
            ulonglong2 A1 = *(const ulonglong2*)(ab + 4);   // row pairs 2,3
            float2 b = *(const float2*)&bs[kl * 128 + tx * 2];
            ull d0 = dup2(b.x), d1 = dup2(b.y);
            u00 = fma2(A0.x, d0, u00); u01 = fma2(A0.x, d1, u01);
            u10 = fma2(A0.y, d0, u10); u11 = fma2(A0.y, d1, u11);
            u20 = fma2(A1.x, d0, u20); u21 = fma2(A1.x, d1, u21);
            u30 = fma2(A1.y, d0, u30); u31 = fma2(A1.y, d1, u31);
        }

        if (kc == 3) {                       // tile complete -> epilogue
            const int ct = g >> 2;
            const int cb = ct * 128 + tx * 2;
            const bool ok = (cb < C_N);      // col pair fully valid or not

#define EPI(UA, UB, RR) do {                                                 \
    float sA0, sB0, sA1, sB1;                                                \
    unpack2(UA, sA0, sB0); unpack2(UB, sA1, sB1);                            \
    int _rl = ty * 8 + (RR);                                                 \
    if (ok) {                                                                \
        *(float2*)&outp[(size_t)(r0 + _rl) * C_N + cb] =                     \
            make_float2(sA0, sA1);                                           \
        *(float2*)&outp[(size_t)(r0 + _rl + 1) * C_N + cb] =                 \
            make_float2(sB0, sB1);                                           \
    }                                                                        \
    float _m = ok ? fmaxf(sA0, sA1) : NEG;                                   \
    _Pragma("unroll")                                                        \
    for (int _d = 1; _d < 32; _d <<= 1)                                      \
        _m = fmaxf(_m, __shfl_xor_sync(0xffffffffu, _m, _d));                \
    float _q = ok ? (__expf(sA0 - _m) + __expf(sA1 - _m)) : 0.f;             \
    _Pragma("unroll")                                                        \
    for (int _d = 1; _d < 32; _d <<= 1)                                      \
        _q += __shfl_xor_sync(0xffffffffu, _q, _d);                          \
    { float _mn = fmaxf(ms[(RR)], _m);                                       \
      ps[(RR)] = ps[(RR)] * __expf(ms[(RR)] - _mn) + _q * __expf(_m - _mn);  \
      ms[(RR)] = _mn; }                                                      \
    float _m2 = ok ? fmaxf(sB0, sB1) : NEG;                                  \
    _Pragma("unroll")                                                        \
    for (int _d = 1; _d < 32; _d <<= 1)                                      \
        _m2 = fmaxf(_m2, __shfl_xor_sync(0xffffffffu, _m2, _d));             \
    float _q2 = ok ? (__expf(sB0 - _m2) + __expf(sB1 - _m2)) : 0.f;          \
    _Pragma("unroll")                                                        \
    for (int _d = 1; _d < 32; _d <<= 1)                                      \
        _q2 += __shfl_xor_sync(0xffffffffu, _q2, _d);                        \
    { float _mn = fmaxf(ms[(RR) + 1], _m2);                                  \
      ps[(RR) + 1] = ps[(RR) + 1] * __expf(ms[(RR) + 1] - _mn)               \
                   + _q2 * __expf(_m2 - _mn);                                \
      ms[(RR) + 1] = _mn; }                                                  \
} while (0)

            EPI(u00, u01, 0);
            EPI(u10, u11, 2);
            EPI(u20, u21, 4);
            EPI(u30, u31, 6);
#undef EPI
            u00 = u01 = u10 = u11 = u20 = u21 = u30 = u31 = 0ull;
        }
        __syncthreads();
    }
#undef STAGE

    // ---- Phase 3: merge per-warp stats (Bs is dead now), normalize ----
    float* fm = Bs;            // [32 rows][2 halves]
    float* fp = Bs + 64;
    float2* rms = (float2*)(Bs + 128);
    const int half = (tid >> 5) & 1;
    if ((tid & 31) == 0) {
#pragma unroll
        for (int rrr = 0; rrr < 8; rrr++) {
            fm[(ty * 8 + rrr) * 2 + half] = ms[rrr];
            fp[(ty * 8 + rrr) * 2 + half] = ps[rrr];
        }
    }
    __syncthreads();
    if (tid < 32) {
        float m0 = fm[tid * 2], m1 = fm[tid * 2 + 1];
        float mm = fmaxf(m0, m1);
        float ss = fp[tid * 2] * __expf(m0 - mm)
                 + fp[tid * 2 + 1] * __expf(m1 - mm);
        rms[tid] = make_float2(mm, 1.f / ss);
    }
    __syncthreads();

    for (int r = 0; r < 32; r++) {
        float2 v2 = rms[r];
        float4* base = (float4*)(outp + (size_t)(r0 + r) * C_N);
        for (int j = tid; j < C_N / 4; j += 256) {
            float4 v = base[j];
            v.x = __expf(v.x - v2.x) * v2.y;
            v.y = __expf(v.y - v2.x) * v2.y;
            v.z = __expf(v.z - v2.x) * v2.y;
            v.w = __expf(v.w - v2.x) * v2.y;
            base[j] = v;
        }
    }
}

// ---------------------------------------------------------------------------
// Launch. x_c^T scratch lives in the dead mc_call_row input buffer
// (640000 int32 == 128*5000 floats exactly; call edges are dead in the
// collapsed math). Fully rewritten every call -> deterministic.
// ---------------------------------------------------------------------------
extern "C" void kernel_launch(void* const* d_in, const int* in_sizes, int n_in,
                              void* d_out, int out_size)
{
    const float* m_feat  = (const float*)d_in[0];
    const float* c_feat  = (const float*)d_in[1];
    const float* own_val = (const float*)d_in[2];
    const float* W1 = (const float*)d_in[3];
    const float* b1 = (const float*)d_in[6];
    const float* W2 = (const float*)d_in[7];
    const float* b2 = (const float*)d_in[10];
    const float* W3 = (const float*)d_in[11];
    const float* b3 = (const float*)d_in[14];
    const int* own_row = (const int*)d_in[15];
    const int* own_col = (const int*)d_in[16];
    float* xcT = (float*)d_in[17];      // dead input -> x_c^T scratch
    float* outp = (float*)d_out;

    k1_kernel<<<313, 128>>>(c_feat, W2, W3, b2, b3, xcT);
    k2_kernel<<<625, 256>>>(m_feat, W1, b1, own_val, own_row, own_col,
                            c_feat, xcT, outp);
}